// round 17
// baseline (speedup 1.0000x reference)
#include <cuda_runtime.h>
#include <cuda_fp16.h>
#include <cstdint>
#include <math.h>

#define BATCH 2
#define SEQ   4096
#define DMODEL 1024
#define NHEAD 4
#define DK    256
#define MS (BATCH * SEQ)
#define SCALE_F (1.0f / 16.0f)
#define DQK (DMODEL + DK)          // 1280: merged Q|K projection width

#define BM 128
#define BN 128
#define TILE_B 16384
#define NTHREADS 128               // 4 warps, 2x2 warp grid, 64x64 warp tile

// 1-phase GEMMs: 2 tiles/stage, 3 stages -> 96KB, 2 CTA/SM
#define STAGES 3
#define STAGE2_B (2 * TILE_B)
#define G1_SMEM (STAGES * STAGE2_B)

// ---------------------------------------------------------------------------
// Device scratch
// ---------------------------------------------------------------------------
__device__ __align__(256) __half g_Xf[(size_t)MS * DMODEL];
__device__ __align__(256) __half g_Wqk[(size_t)DQK * DMODEL];   // Wq rows 0-1023, Wk rows 1024-1279
__device__ __align__(256) __half g_Wv[(size_t)DK * DMODEL];
__device__ __align__(256) __half g_Wo[(size_t)DMODEL * DMODEL];
__device__ __align__(256) __half g_QK[(size_t)MS * DQK];        // Q cols 0-1023, K cols 1024-1279
__device__ __align__(256) __half g_Vt[(size_t)BATCH * DK * SEQ];
__device__ __align__(256) __half g_S[(size_t)BATCH * NHEAD * SEQ * SEQ];
__device__ __align__(256) __half g_M[(size_t)MS * DMODEL];
__device__ __align__(256) float  g_rowsum[(size_t)BATCH * NHEAD * SEQ];

// ---------------------------------------------------------------------------
// PTX helpers
// ---------------------------------------------------------------------------
__device__ __forceinline__ uint32_t smem_u32(const void* p) {
    uint32_t a;
    asm("{ .reg .u64 t; cvta.to.shared.u64 t, %1; cvt.u32.u64 %0, t; }"
        : "=r"(a) : "l"(p));
    return a;
}
__device__ __forceinline__ void cp16(uint32_t s, const void* g) {
    asm volatile("cp.async.cg.shared.global [%0], [%1], 16;" :: "r"(s), "l"(g));
}
#define CP_COMMIT() asm volatile("cp.async.commit_group;" ::: "memory")
#define CP_WAIT2()  asm volatile("cp.async.wait_group 2;" ::: "memory")

__device__ __forceinline__ void ldsm4(uint32_t* r, uint32_t addr) {
    asm volatile("ldmatrix.sync.aligned.m8n8.x4.shared.b16 {%0,%1,%2,%3}, [%4];"
                 : "=r"(r[0]), "=r"(r[1]), "=r"(r[2]), "=r"(r[3]) : "r"(addr));
}
__device__ __forceinline__ void mma_f16(float* c, const uint32_t* a,
                                        uint32_t b0, uint32_t b1) {
    asm volatile(
        "mma.sync.aligned.m16n8k16.row.col.f32.f16.f16.f32 "
        "{%0,%1,%2,%3}, {%4,%5,%6,%7}, {%8,%9}, {%0,%1,%2,%3};\n"
        : "+f"(c[0]), "+f"(c[1]), "+f"(c[2]), "+f"(c[3])
        : "r"(a[0]), "r"(a[1]), "r"(a[2]), "r"(a[3]), "r"(b0), "r"(b1));
}

// ---------------------------------------------------------------------------
// Shared GEMM body, templated on leading dimensions. ks-level fragment
// double-buffering: fragments for step ks+1 are issued BEFORE the MMAs of
// step ks so LDSM latency overlaps HMMA issue (the JIT kept them
// just-in-time; issue stalled at 33% with only 2 warps/SMSP).
// MMA order unchanged -> bit-identical math.
// fuse 0: fp16 out. fuse 1: out = exp(alpha*acc) fp16 + rowsum atomics.
// fuse 2: out = acc / rowsum[row] fp16. fuse 3: fp32 out.
// ---------------------------------------------------------------------------
template <int LDA, int LDB>
__device__ __forceinline__ void gemm_body(
    const __half* __restrict__ A_, const __half* __restrict__ B_,
    __half* __restrict__ Hf, float* __restrict__ Cf,
    float* __restrict__ rowsum, int fuse,
    int nK, int ldc, float alpha,
    int rowBase, int colBase, uint32_t sbase)
{
    const int tid = threadIdx.x;
    const int wid = tid >> 5;          // 0..3
    const int lid = tid & 31;
    const int warpM = (wid >> 1) * 64; // 2x2 warp grid
    const int warpN = (wid & 1) * 64;

    // ldsm addressing (swizzle invariant across fragments at fixed ks)
    const int c0 = lid >> 4;
    const int r7 = lid & 7;
    uint32_t swoff[4];
#pragma unroll
    for (int ks = 0; ks < 4; ks++)
        swoff[ks] = (uint32_t)(((((ks * 2) | c0) ^ r7) << 4));
    uint32_t rtA[4], rtB[4];
#pragma unroll
    for (int i = 0; i < 4; i++)
        rtA[i] = (uint32_t)((warpM + i * 16 + (lid & 15)) * 128);
#pragma unroll
    for (int jg = 0; jg < 4; jg++)
        rtB[jg] = (uint32_t)(TILE_B + (warpN + jg * 16 + (lid & 15)) * 128);

    // cp.async addressing: thread-constant smem offset + immediate j terms
    const int lrow = tid >> 3;                       // 0..15
    const int cc = tid & 7;
    const uint32_t so = (uint32_t)(lrow * 128 + ((cc ^ (lrow & 7)) << 4));
    const __half* gA = A_ + (long long)lrow * LDA + cc * 8;
    const __half* gB = B_ + (long long)lrow * LDB + cc * 8;

    float acc[4][8][4];
#pragma unroll
    for (int i = 0; i < 4; i++)
#pragma unroll
        for (int j = 0; j < 8; j++)
#pragma unroll
            for (int v = 0; v < 4; v++) acc[i][j][v] = 0.0f;

    auto load_stage = [&](int t, int buf) {
        const __half* pA = gA + (long long)t * 64;
        const __half* pB = gB + (long long)t * 64;
        const uint32_t tbA = sbase + buf * STAGE2_B + so;
        const uint32_t tbB = tbA + TILE_B;
#pragma unroll
        for (int j = 0; j < 8; j++)
            cp16(tbA + j * 2048, pA + (long long)j * 16 * LDA);
#pragma unroll
        for (int j = 0; j < 8; j++)
            cp16(tbB + j * 2048, pB + (long long)j * 16 * LDB);
    };

#pragma unroll
    for (int s = 0; s < STAGES; s++) {
        if (s < nK) load_stage(s, s);
        CP_COMMIT();
    }

    for (int t = 0; t < nK; t++) {
        const int buf = t % STAGES;
        CP_WAIT2();
        __syncthreads();

        const uint32_t sS = sbase + buf * STAGE2_B;

        // ks-pipelined fragments: double-buffered register sets
        uint32_t a[2][4][4], b[2][4][4];
#pragma unroll
        for (int i = 0; i < 4; i++)
            ldsm4(a[0][i], sS + rtA[i] + swoff[0]);
#pragma unroll
        for (int jg = 0; jg < 4; jg++)
            ldsm4(b[0][jg], sS + rtB[jg] + swoff[0]);

#pragma unroll
        for (int ks = 0; ks < 4; ks++) {
            const int cur = ks & 1;
            const int nxt = cur ^ 1;
            if (ks < 3) {
#pragma unroll
                for (int i = 0; i < 4; i++)
                    ldsm4(a[nxt][i], sS + rtA[i] + swoff[ks + 1]);
#pragma unroll
                for (int jg = 0; jg < 4; jg++)
                    ldsm4(b[nxt][jg], sS + rtB[jg] + swoff[ks + 1]);
            }
#pragma unroll
            for (int i = 0; i < 4; i++) {
#pragma unroll
                for (int j = 0; j < 8; j++) {
                    mma_f16(acc[i][j], a[cur][i],
                            b[cur][j >> 1][j & 1], b[cur][j >> 1][(j & 1) + 2]);
                }
            }
        }
        __syncthreads();

        const int nt = t + STAGES;
        if (nt < nK) load_stage(nt, buf);
        CP_COMMIT();
    }

    const int g = lid >> 2;
    const int tq = lid & 3;

#pragma unroll
    for (int i = 0; i < 4; i++) {
        const int lr0 = rowBase + warpM + i * 16 + g;
        const int lr1 = lr0 + 8;
        const long long r0 = lr0, r1 = lr1;

        float inv0 = 1.0f, inv1 = 1.0f;
        if (fuse == 2) {
            inv0 = __frcp_rn(rowsum[lr0]);
            inv1 = __frcp_rn(rowsum[lr1]);
        }
        float se0 = 0.0f, se1 = 0.0f;

#pragma unroll
        for (int j = 0; j < 8; j++) {
            const int col = colBase + warpN + j * 8 + tq * 2;
            float x0 = acc[i][j][0] * alpha, x1 = acc[i][j][1] * alpha;
            float x2 = acc[i][j][2] * alpha, x3 = acc[i][j][3] * alpha;
            if (fuse == 1) {
                x0 = __expf(x0); x1 = __expf(x1);
                x2 = __expf(x2); x3 = __expf(x3);
                se0 += x0 + x1;
                se1 += x2 + x3;
            } else if (fuse == 2) {
                x0 *= inv0; x1 *= inv0;
                x2 *= inv1; x3 *= inv1;
            }
            if (fuse == 3) {
                *reinterpret_cast<float2*>(Cf + r0 * ldc + col) =
                    make_float2(x0, x1);
                *reinterpret_cast<float2*>(Cf + r1 * ldc + col) =
                    make_float2(x2, x3);
            } else {
                *reinterpret_cast<__half2*>(Hf + r0 * ldc + col) =
                    __floats2half2_rn(x0, x1);
                *reinterpret_cast<__half2*>(Hf + r1 * ldc + col) =
                    __floats2half2_rn(x2, x3);
            }
        }

        if (fuse == 1) {
            se0 += __shfl_xor_sync(0xffffffffu, se0, 1);
            se0 += __shfl_xor_sync(0xffffffffu, se0, 2);
            se1 += __shfl_xor_sync(0xffffffffu, se1, 1);
            se1 += __shfl_xor_sync(0xffffffffu, se1, 2);
            if (tq == 0) {
                atomicAdd(&rowsum[lr0], se0);
                atomicAdd(&rowsum[lr1], se1);
            }
        }
    }
}

// ---------------------------------------------------------------------------
// Generic batched GEMM kernel (QK, PV, O-proj), templated on lds.
// ---------------------------------------------------------------------------
template <int LDA, int LDB>
__global__ void __launch_bounds__(NTHREADS, 2)
gemm_f16(const __half* __restrict__ A, const __half* __restrict__ B,
         __half* __restrict__ Hf, float* __restrict__ Cf,
         float* __restrict__ rowsum, int fuse,
         int K, int ldc, float alpha,
         long long aSB, long long aSH, long long bSB, long long bSH,
         long long cSB, long long cSH, int H)
{
    extern __shared__ char smem[];
    const uint32_t sbase = smem_u32(smem);

    const int zb = blockIdx.z / H;
    const int zh = blockIdx.z - zb * H;
    const int rowBase = blockIdx.y * BM;
    const int colBase = blockIdx.x * BN;

    const __half* A_ = A + zb * aSB + zh * aSH + (long long)rowBase * LDA;
    const __half* B_ = B + zb * bSB + zh * bSH + (long long)colBase * LDB;
    const long long cOff = zb * cSB + zh * cSH;

    gemm_body<LDA, LDB>(A_, B_,
                        Hf ? Hf + cOff : nullptr,
                        Cf ? Cf + cOff : nullptr,
                        rowsum + (long long)blockIdx.z * SEQ, fuse,
                        K >> 6, ldc, alpha, rowBase, colBase, sbase);
}

// ---------------------------------------------------------------------------
// Merged projection kernel: one launch covers QK-proj and V-proj.
//   bid <  640: QK-proj  QKbuf = Xf @ Wqk^T  (grid 10 x 64)
//   bid >= 640: V-proj   Vt[b] = Wv @ Xf[b]^T (2 batches x (32 x 2))
// ---------------------------------------------------------------------------
__global__ void __launch_bounds__(NTHREADS, 2)
proj_merged(const __half* __restrict__ Xf, const __half* __restrict__ Wqk,
            const __half* __restrict__ Wv, __half* __restrict__ QKb,
            __half* __restrict__ Vt)
{
    extern __shared__ char smem[];
    const uint32_t sbase = smem_u32(smem);
    const int bid = blockIdx.x;

    if (bid < 640) {
        const int x = bid % (DQK / BN);       // 0..9
        const int y = bid / (DQK / BN);       // 0..63
        const int rowBase = y * BM;
        const int colBase = x * BN;
        gemm_body<DMODEL, DMODEL>(
            Xf + (long long)rowBase * DMODEL,
            Wqk + (long long)colBase * DMODEL,
            QKb, nullptr, nullptr, 0,
            DMODEL >> 6, DQK, 1.0f, rowBase, colBase, sbase);
    } else {
        const int t = bid - 640;
        const int zb = t / 64;                // batch
        const int rem = t - zb * 64;
        const int x = rem % (SEQ / BN);       // 0..31
        const int y = rem / (SEQ / BN);       // 0..1
        const int rowBase = y * BM;
        const int colBase = x * BN;
        gemm_body<DMODEL, DMODEL>(
            Wv + (long long)rowBase * DMODEL,
            Xf + (long long)zb * SEQ * DMODEL + (long long)colBase * DMODEL,
            Vt + (long long)zb * DK * SEQ, nullptr, nullptr, 0,
            DMODEL >> 6, SEQ, 1.0f, rowBase, colBase, sbase);
    }
}

// ---------------------------------------------------------------------------
// Merged split kernel: all fp32->fp16 conversions + rowsum zeroing, 1 launch.
//   [0, 8192)        X  -> Xf
//   [8192, 9216)     Wq -> Wqk rows 0-1023
//   [9216, 9472)     Wk -> Wqk rows 1024-1279
//   [9472, 9728)     Wv -> Wvf
//   [9728, 10752)    Wo -> Wof
//   [10752, 10784)   zero g_rowsum
// ---------------------------------------------------------------------------
__global__ void __launch_bounds__(256)
split_all(const float* __restrict__ X,  const float* __restrict__ Wq,
          const float* __restrict__ Wk, const float* __restrict__ Wv,
          const float* __restrict__ Wo,
          __half* __restrict__ Xf, __half* __restrict__ Wqk,
          __half* __restrict__ Wvf, __half* __restrict__ Wof,
          float* __restrict__ rowsum)
{
    const int bid = blockIdx.x;
    const int tid = threadIdx.x;

    const float* src;
    __half* dst;
    long long i;

    if (bid < 8192) {
        src = X;  dst = Xf;  i = (long long)bid * 256 + tid;
    } else if (bid < 9216) {
        src = Wq; dst = Wqk; i = (long long)(bid - 8192) * 256 + tid;
    } else if (bid < 9472) {
        src = Wk; dst = Wqk + (size_t)DMODEL * DMODEL;
        i = (long long)(bid - 9216) * 256 + tid;
    } else if (bid < 9728) {
        src = Wv; dst = Wvf; i = (long long)(bid - 9472) * 256 + tid;
    } else if (bid < 10752) {
        src = Wo; dst = Wof; i = (long long)(bid - 9728) * 256 + tid;
    } else {
        long long z = (long long)(bid - 10752) * 256 + tid;
        reinterpret_cast<float4*>(rowsum)[z] = make_float4(0.f, 0.f, 0.f, 0.f);
        return;
    }

    float4 v = reinterpret_cast<const float4*>(src)[i];
    __half2 a, b;
    a.x = __float2half(v.x); a.y = __float2half(v.y);
    b.x = __float2half(v.z); b.y = __float2half(v.w);
    reinterpret_cast<__half2*>(dst)[2 * i] = a;
    reinterpret_cast<__half2*>(dst)[2 * i + 1] = b;
}

static void* sym_addr(const void* symbol)
{
    void* p = nullptr;
    cudaGetSymbolAddress(&p, symbol);
    return p;
}

extern "C" void kernel_launch(void* const* d_in, const int* in_sizes, int n_in,
                              void* d_out, int out_size)
{
    const float* X  = (const float*)d_in[0];
    const float* Wq = (const float*)d_in[1];
    const float* Wk = (const float*)d_in[2];
    const float* Wv = (const float*)d_in[3];
    const float* Wo = (const float*)d_in[4];
    float* out = (float*)d_out;

    __half* Xf  = (__half*)sym_addr(g_Xf);
    __half* Wqk = (__half*)sym_addr(g_Wqk);
    __half* Wvf = (__half*)sym_addr(g_Wv);
    __half* Wof = (__half*)sym_addr(g_Wo);
    __half* QKb = (__half*)sym_addr(g_QK);
    __half* Vt  = (__half*)sym_addr(g_Vt);
    __half* S   = (__half*)sym_addr(g_S);
    __half* M   = (__half*)sym_addr(g_M);
    float*  rs  = (float*)sym_addr(g_rowsum);

    cudaFuncSetAttribute(gemm_f16<DQK, DQK>,
                         cudaFuncAttributeMaxDynamicSharedMemorySize, G1_SMEM);
    cudaFuncSetAttribute(gemm_f16<SEQ, SEQ>,
                         cudaFuncAttributeMaxDynamicSharedMemorySize, G1_SMEM);
    cudaFuncSetAttribute(gemm_f16<DMODEL, DMODEL>,
                         cudaFuncAttributeMaxDynamicSharedMemorySize, G1_SMEM);
    cudaFuncSetAttribute(proj_merged,
                         cudaFuncAttributeMaxDynamicSharedMemorySize, G1_SMEM);

    // 1 launch: all fp32->fp16 splits + rowsum zeroing
    split_all<<<10784, 256>>>(X, Wq, Wk, Wv, Wo, Xf, Wqk, Wvf, Wof, rs);

    // 1 launch: QK-proj (merged Q|K) + V-proj
    proj_merged<<<768, NTHREADS, G1_SMEM>>>(Xf, Wqk, Wvf, QKb, Vt);

    // S[b,h] = exp(SCALE * Q[b,h] @ K[b]^T) -> fp16, rowsum accumulated
    gemm_f16<DQK, DQK><<<dim3(SEQ / BN, SEQ / BM, BATCH * NHEAD), NTHREADS,
                         G1_SMEM>>>(
        QKb, QKb + DMODEL, S, nullptr, rs, 1,
        DK, SEQ, SCALE_F,
        (long long)SEQ * DQK, DK,
        (long long)SEQ * DQK, 0,
        (long long)NHEAD * SEQ * SEQ, (long long)SEQ * SEQ, NHEAD);

    // M = (S @ VcT^T) / rowsum -> fp16 merged [8192 x 1024]
    gemm_f16<SEQ, SEQ><<<dim3(DK / BN, SEQ / BM, BATCH * NHEAD), NTHREADS,
                         G1_SMEM>>>(
        S, Vt, M, nullptr, rs, 2,
        SEQ, DMODEL, 1.0f,
        (long long)NHEAD * SEQ * SEQ, (long long)SEQ * SEQ,
        (long long)DK * SEQ, 0,
        (long long)SEQ * DMODEL, DK, NHEAD);

    // out = M @ Wo^T -> fp32 (1-phase)
    gemm_f16<DMODEL, DMODEL><<<dim3(DMODEL / BN, MS / BM, 1), NTHREADS,
                               G1_SMEM>>>(
        M, Wof, nullptr, out, rs, 3,
        DMODEL, DMODEL, 1.0f,
        0, 0, 0, 0, 0, 0, 1);
}